// round 1
// baseline (speedup 1.0000x reference)
#include <cuda_runtime.h>
#include <math.h>

#define NQ     16384
#define NM     16384
#define DIM    128
#define KNN    5
#define BLK    128          // query tile and m tile
#define BD     16           // d-chunk staged in smem
#define MCHUNK 2048         // memory rows per CTA
#define NMCH   (NM / MCHUNK)   // 8 candidate chunks per query
#define PITCH  132          // smem pitch (floats), multiple of 4, 33 banks-ish
#define TPB    256

#define FLT_BIG 3.402823466e+38f

// Scratch (no allocation allowed -> device globals)
__device__ float g_q2[NQ];
__device__ float g_m2[NM];
__device__ float g_cd[(size_t)NQ * NMCH * KNN];
__device__ int   g_ci[(size_t)NQ * NMCH * KNN];

// ---------------------------------------------------------------------------
// Row norms for query and memory bank (NQ == NM so one kernel covers both)
// ---------------------------------------------------------------------------
__global__ void norms_kernel(const float* __restrict__ q,
                             const float* __restrict__ mb) {
    int i = blockIdx.x * blockDim.x + threadIdx.x;
    if (i >= NQ) return;
    const float4* p = reinterpret_cast<const float4*>(q) + (size_t)i * (DIM / 4);
    float s = 0.f;
#pragma unroll
    for (int j = 0; j < DIM / 4; ++j) {
        float4 v = p[j];
        s = fmaf(v.x, v.x, s); s = fmaf(v.y, v.y, s);
        s = fmaf(v.z, v.z, s); s = fmaf(v.w, v.w, s);
    }
    g_q2[i] = s;

    const float4* pm = reinterpret_cast<const float4*>(mb) + (size_t)i * (DIM / 4);
    s = 0.f;
#pragma unroll
    for (int j = 0; j < DIM / 4; ++j) {
        float4 v = pm[j];
        s = fmaf(v.x, v.x, s); s = fmaf(v.y, v.y, s);
        s = fmaf(v.z, v.z, s); s = fmaf(v.w, v.w, s);
    }
    g_m2[i] = s;
}

// ---------------------------------------------------------------------------
// Phase 1: tiled distance GEMM with fused per-tile top-5 scan.
// Each CTA: 128 queries x 2048 memory rows. Candidate metric stored is
// (m^2 - 2*q.m); q^2 is a per-query constant added in phase 2.
// ---------------------------------------------------------------------------
__global__ void __launch_bounds__(TPB, 2)
knn_tile_kernel(const float* __restrict__ query,
                const float* __restrict__ mbank) {
    extern __shared__ float smem[];
    float* Qs   = smem;                       // [BD][PITCH]   (d-major, q inner)
    float* Ms   = smem + BD * PITCH;          // [BD][PITCH]   (d-major, m inner)
    float* Dist = smem + 2 * BD * PITCH;      // [BLK][PITCH]  (m-major, q inner)

    const int qbase  = blockIdx.x * BLK;
    const int mchunk = blockIdx.y;
    const int tid = threadIdx.x;
    const int tx  = tid & 15;       // m direction (8 cols each)
    const int ty  = tid >> 4;       // q direction (8 rows each)

    // private top-5 (ascending) for scan threads (tid < 128 owns query qbase+tid)
    float b[KNN];
    int   bi[KNN];
#pragma unroll
    for (int r = 0; r < KNN; ++r) { b[r] = FLT_BIG; bi[r] = 0; }

    for (int mt = 0; mt < MCHUNK / BLK; ++mt) {
        const int mbase = mchunk * MCHUNK + mt * BLK;

        float acc[8][8];
#pragma unroll
        for (int i = 0; i < 8; ++i)
#pragma unroll
            for (int j = 0; j < 8; ++j) acc[i][j] = 0.f;

        for (int dc = 0; dc < DIM; dc += BD) {
            __syncthreads();   // previous users of Qs/Ms (and prior scan) done
            // Stage BD x 128 slices of Q and M, transposed to d-major.
            // f = tid + 256*l covers 512 float4 loads, fully coalesced.
#pragma unroll
            for (int l = 0; l < 2; ++l) {
                int f   = tid + TPB * l;
                int row = f >> 2;
                int d4  = (f & 3) * 4;
                float4 v = *reinterpret_cast<const float4*>(
                    query + (size_t)(qbase + row) * DIM + dc + d4);
                Qs[(d4 + 0) * PITCH + row] = v.x;
                Qs[(d4 + 1) * PITCH + row] = v.y;
                Qs[(d4 + 2) * PITCH + row] = v.z;
                Qs[(d4 + 3) * PITCH + row] = v.w;
                float4 w = *reinterpret_cast<const float4*>(
                    mbank + (size_t)(mbase + row) * DIM + dc + d4);
                Ms[(d4 + 0) * PITCH + row] = w.x;
                Ms[(d4 + 1) * PITCH + row] = w.y;
                Ms[(d4 + 2) * PITCH + row] = w.z;
                Ms[(d4 + 3) * PITCH + row] = w.w;
            }
            __syncthreads();

#pragma unroll
            for (int kk = 0; kk < BD; ++kk) {
                float4 qa = *reinterpret_cast<const float4*>(&Qs[kk * PITCH + ty * 8]);
                float4 qb = *reinterpret_cast<const float4*>(&Qs[kk * PITCH + ty * 8 + 4]);
                float4 ma = *reinterpret_cast<const float4*>(&Ms[kk * PITCH + tx * 8]);
                float4 mb4 = *reinterpret_cast<const float4*>(&Ms[kk * PITCH + tx * 8 + 4]);
                float qr[8] = {qa.x, qa.y, qa.z, qa.w, qb.x, qb.y, qb.z, qb.w};
                float mr[8] = {ma.x, ma.y, ma.z, ma.w, mb4.x, mb4.y, mb4.z, mb4.w};
#pragma unroll
                for (int i = 0; i < 8; ++i)
#pragma unroll
                    for (int j = 0; j < 8; ++j)
                        acc[i][j] = fmaf(qr[i], mr[j], acc[i][j]);
            }
        }

        // write candidate metric m2 - 2*dot, m-major so the scan is conflict-free
#pragma unroll
        for (int j = 0; j < 8; ++j) {
            int   mj  = tx * 8 + j;
            float m2v = g_m2[mbase + mj];
#pragma unroll
            for (int i = 0; i < 8; ++i) {
                Dist[mj * PITCH + ty * 8 + i] = fmaf(-2.f, acc[i][j], m2v);
            }
        }
        __syncthreads();

        if (tid < BLK) {
#pragma unroll 4
            for (int j = 0; j < BLK; ++j) {
                float c = Dist[j * PITCH + tid];
                if (c < b[KNN - 1]) {
                    b[KNN - 1]  = c;
                    bi[KNN - 1] = mbase + j;
#pragma unroll
                    for (int r = KNN - 1; r > 0; --r) {
                        if (b[r] < b[r - 1]) {
                            float tf = b[r]; b[r] = b[r - 1]; b[r - 1] = tf;
                            int   ti = bi[r]; bi[r] = bi[r - 1]; bi[r - 1] = ti;
                        }
                    }
                }
            }
        }
        // next iteration's first __syncthreads orders scan vs. Qs/Ms overwrite;
        // Dist is only overwritten after a further sync.
    }

    if (tid < BLK) {
        int q = qbase + tid;
        size_t base = ((size_t)q * NMCH + mchunk) * KNN;
#pragma unroll
        for (int r = 0; r < KNN; ++r) {
            g_cd[base + r] = b[r];
            g_ci[base + r] = bi[r];
        }
    }
}

// ---------------------------------------------------------------------------
// Phase 2: merge 8x5 candidates per query -> final top-5, compute output.
// ---------------------------------------------------------------------------
__global__ void finalize_kernel(const float* __restrict__ scale,
                                float* __restrict__ out) {
    int q = blockIdx.x * blockDim.x + threadIdx.x;
    if (q >= NQ) return;

    float b[KNN];
    int   bi[KNN];
#pragma unroll
    for (int r = 0; r < KNN; ++r) { b[r] = FLT_BIG; bi[r] = 0; }

    size_t base = (size_t)q * NMCH * KNN;
    for (int c = 0; c < NMCH * KNN; ++c) {
        float v  = g_cd[base + c];
        if (v < b[KNN - 1]) {
            int vi = g_ci[base + c];
            b[KNN - 1]  = v;
            bi[KNN - 1] = vi;
#pragma unroll
            for (int r = KNN - 1; r > 0; --r) {
                if (b[r] < b[r - 1]) {
                    float tf = b[r]; b[r] = b[r - 1]; b[r - 1] = tf;
                    int   ti = bi[r]; bi[r] = bi[r - 1]; bi[r - 1] = ti;
                }
            }
        }
    }

    float q2v = g_q2[q];
    float d[KNN];
#pragma unroll
    for (int r = 0; r < KNN; ++r)
        d[r] = sqrtf(fmaxf(q2v + b[r], 1e-12f));

    // softmax(-d / T), T = 1; d[] ascending so d[0] is the max logit
    float W = 0.f, wd = 0.f;
#pragma unroll
    for (int r = 0; r < KNN; ++r) {
        float e = expf(d[0] - d[r]);
        W  += e;
        wd += e * d[r];
    }
    wd /= W;

    float ns = 0.f;
#pragma unroll
    for (int r = 0; r < KNN; ++r) ns += scale[bi[r]];
    ns *= (1.f / KNN);
    float nd = wd / fmaxf(ns, 1e-6f);

    float mean = 0.f;
#pragma unroll
    for (int r = 0; r < KNN; ++r) mean += d[r];
    mean *= (1.f / KNN);
    float var = 0.f;
#pragma unroll
    for (int r = 0; r < KNN; ++r) { float t = d[r] - mean; var = fmaf(t, t, var); }
    var *= (1.f / KNN);
    float cons = sqrtf(fmaxf(var, 0.f)) / fmaxf(mean, 1e-6f);

    out[q] = nd * (1.f + 0.5f * cons);
}

// ---------------------------------------------------------------------------
// Launch
// ---------------------------------------------------------------------------
extern "C" void kernel_launch(void* const* d_in, const int* in_sizes, int n_in,
                              void* d_out, int out_size) {
    const float* query = (const float*)d_in[0];
    const float* mbank = (const float*)d_in[1];
    const float* scale = (const float*)d_in[2];
    float* out = (float*)d_out;
    (void)in_sizes; (void)n_in; (void)out_size;

    static const size_t smem_bytes = (size_t)(2 * BD + BLK) * PITCH * sizeof(float);
    cudaFuncSetAttribute(knn_tile_kernel,
                         cudaFuncAttributeMaxDynamicSharedMemorySize,
                         (int)smem_bytes);

    norms_kernel<<<(NQ + 255) / 256, 256>>>(query, mbank);

    dim3 grid(NQ / BLK, NMCH);
    knn_tile_kernel<<<grid, TPB, smem_bytes>>>(query, mbank);

    finalize_kernel<<<(NQ + 255) / 256, 256>>>(scale, out);
}

// round 3
// speedup vs baseline: 2.1424x; 2.1424x over previous
#include <cuda_runtime.h>
#include <cuda_bf16.h>
#include <cstdint>
#include <math.h>

#define NQ    16384
#define NM    16384
#define DIM   128
#define KNN   5
#define KSPLIT 384
#define KC    64                   // bf16 K per chunk (128B per row)
#define NKC   (KSPLIT / KC)        // 6
#define TILES (NM / 128)           // 128
#define CHUNK_BYTES 16384          // 128 rows * 128 B
#define BLOCK_BYTES (NKC * CHUNK_BYTES)

#define AS_OFF   0                 // 96 KB resident A
#define BS_OFF   98304             // 2 x 16 KB B double buffer
#define DIST_OFF 131072            // 128 x 132 x 4 = 67584
#define PITCH    132
#define SMEM_TOTAL (DIST_OFF + 128 * PITCH * 4)

#define FLT_BIG 3.402823466e+38f

// device scratch (no allocation allowed)
__device__ __align__(128) unsigned char g_B[(size_t)TILES * BLOCK_BYTES];
__device__ float g_m2[NM];

// ---------------------------------------------------------------------------
// helpers
// ---------------------------------------------------------------------------
__device__ __forceinline__ uint32_t smem_u32(const void* p) {
    uint32_t a;
    asm("{ .reg .u64 t; cvta.to.shared.u64 t, %1; cvt.u32.u64 %0, t; }" : "=r"(a) : "l"(p));
    return a;
}

// byte offset of (row r, bf16 col k) in the [NKC][128 rows][128B] chunked,
// xor-swizzled layout (swizzled 16B column = (k>>3) ^ (r&7))
__device__ __forceinline__ uint32_t goff(int r, int k) {
    int kc = k >> 6, kl = k & 63;
    return (uint32_t)(kc * CHUNK_BYTES + r * 128 + ((((kl >> 3) ^ (r & 7))) << 4) + ((kl & 7) << 1));
}

__device__ __forceinline__ void split2(float a, float b, uint32_t& hi2, uint32_t& lo2) {
    __nv_bfloat16 ah = __float2bfloat16(a);
    __nv_bfloat16 bh = __float2bfloat16(b);
    __nv_bfloat16 al = __float2bfloat16(a - __bfloat162float(ah));
    __nv_bfloat16 bl = __float2bfloat16(b - __bfloat162float(bh));
    hi2 = (uint32_t)__bfloat16_as_ushort(ah) | ((uint32_t)__bfloat16_as_ushort(bh) << 16);
    lo2 = (uint32_t)__bfloat16_as_ushort(al) | ((uint32_t)__bfloat16_as_ushort(bl) << 16);
}

__device__ __forceinline__ void cpa16(uint32_t dst, const void* src) {
    asm volatile("cp.async.cg.shared.global [%0], [%1], 16;" :: "r"(dst), "l"(src));
}

#define LDSM_X4(r0, r1, r2, r3, addr) \
    asm volatile("ldmatrix.sync.aligned.m8n8.x4.shared.b16 {%0,%1,%2,%3}, [%4];" \
        : "=r"(r0), "=r"(r1), "=r"(r2), "=r"(r3) : "r"(addr))

#define MMA16816(d, a, b0, b1) \
    asm volatile("mma.sync.aligned.m16n8k16.row.col.f32.bf16.bf16.f32 " \
        "{%0,%1,%2,%3}, {%4,%5,%6,%7}, {%8,%9}, {%0,%1,%2,%3};" \
        : "+f"((d)[0]), "+f"((d)[1]), "+f"((d)[2]), "+f"((d)[3]) \
        : "r"((a)[0]), "r"((a)[1]), "r"((a)[2]), "r"((a)[3]), "r"(b0), "r"(b1))

// ---------------------------------------------------------------------------
// Prepass: memory bank -> swizzled bf16 split blocks (B = [hi | hi | lo]) + m2
// ---------------------------------------------------------------------------
__global__ void __launch_bounds__(256)
prepass_kernel(const float* __restrict__ mbank) {
    int i = blockIdx.x * 256 + threadIdx.x;
    int t = i >> 7, r = i & 127;
    unsigned char* blk = g_B + (size_t)t * BLOCK_BYTES;
    const float4* row = reinterpret_cast<const float4*>(mbank + (size_t)i * DIM);
    float m2 = 0.f;
#pragma unroll
    for (int j = 0; j < 32; ++j) {
        float4 v = row[j];
        m2 = fmaf(v.x, v.x, m2); m2 = fmaf(v.y, v.y, m2);
        m2 = fmaf(v.z, v.z, m2); m2 = fmaf(v.w, v.w, m2);
        int d0 = j * 4;
        uint32_t h, l;
        split2(v.x, v.y, h, l);
        *(uint32_t*)(blk + goff(r, d0))       = h;
        *(uint32_t*)(blk + goff(r, 128 + d0)) = h;
        *(uint32_t*)(blk + goff(r, 256 + d0)) = l;
        split2(v.z, v.w, h, l);
        *(uint32_t*)(blk + goff(r, d0 + 2))       = h;
        *(uint32_t*)(blk + goff(r, 128 + d0 + 2)) = h;
        *(uint32_t*)(blk + goff(r, 256 + d0 + 2)) = l;
    }
    g_m2[i] = m2;
}

// ---------------------------------------------------------------------------
// Main kernel: 128 CTAs x 128 queries, sweep all memory tiles with HMMA
// ---------------------------------------------------------------------------
__global__ void __launch_bounds__(256, 1)
knn_main(const float* __restrict__ query,
         const float* __restrict__ scale,
         float* __restrict__ out) {
    extern __shared__ char smem[];
    const uint32_t sb = smem_u32(smem);
    const int tid  = threadIdx.x;
    const int lane = tid & 31;
    const int wid  = tid >> 5;
    const int wq   = wid >> 2;          // 0..1 : query 64-row half
    const int wx   = wid & 3;           // 0..3 : m 32-col slice
    const int qbase = blockIdx.x * 128;

    // ---- kick off first B chunk copy ----
    {
        const unsigned char* src = g_B;     // tile 0, chunk 0
        uint32_t dst = sb + BS_OFF;
#pragma unroll
        for (int p = 0; p < 4; ++p)
            cpa16(dst + p * 4096 + tid * 16, src + p * 4096 + tid * 16);
        asm volatile("cp.async.commit_group;" ::: "memory");
    }

    // ---- convert A = -2q split (hi | lo | hi) into resident smem ----
    float q2 = 0.f;
    if (tid < 128) {
        const float4* row = reinterpret_cast<const float4*>(query + (size_t)(qbase + tid) * DIM);
#pragma unroll
        for (int j = 0; j < 32; ++j) {
            float4 v = row[j];
            q2 = fmaf(v.x, v.x, q2); q2 = fmaf(v.y, v.y, q2);
            q2 = fmaf(v.z, v.z, q2); q2 = fmaf(v.w, v.w, q2);
            int d0 = j * 4;
            uint32_t h, l;
            split2(-2.f * v.x, -2.f * v.y, h, l);
            *(uint32_t*)(smem + AS_OFF + goff(tid, d0))       = h;
            *(uint32_t*)(smem + AS_OFF + goff(tid, 128 + d0)) = l;
            *(uint32_t*)(smem + AS_OFF + goff(tid, 256 + d0)) = h;
            split2(-2.f * v.z, -2.f * v.w, h, l);
            *(uint32_t*)(smem + AS_OFF + goff(tid, d0 + 2))       = h;
            *(uint32_t*)(smem + AS_OFF + goff(tid, 128 + d0 + 2)) = l;
            *(uint32_t*)(smem + AS_OFF + goff(tid, 256 + d0 + 2)) = h;
        }
    }

    // per-warp ldmatrix base addresses
    const int r_l = lane & 15;
    const int cb  = lane >> 4;
    uint32_t abase[4]; int axor[4];
#pragma unroll
    for (int mi = 0; mi < 4; ++mi) {
        int row = wq * 64 + mi * 16 + r_l;
        abase[mi] = sb + AS_OFF + (uint32_t)row * 128;
        axor[mi]  = row & 7;
    }
    uint32_t bbase[2]; int bxor[2];
#pragma unroll
    for (int nh = 0; nh < 2; ++nh) {
        int row = wx * 32 + nh * 16 + r_l;
        bbase[nh] = sb + BS_OFF + (uint32_t)row * 128;
        bxor[nh]  = row & 7;
    }

    float* Dist = reinterpret_cast<float*>(smem + DIST_OFF);
    const int scan_q = tid & 127;
    const int scan_h = tid >> 7;

    float best[KNN]; int bidx[KNN];
#pragma unroll
    for (int s = 0; s < KNN; ++s) { best[s] = FLT_BIG; bidx[s] = 0; }

    __syncthreads();   // A resident before first compute

    int cnt = 0;       // global chunk counter
    for (int t = 0; t < TILES; ++t) {
        float acc[4][4][4];
#pragma unroll
        for (int mi = 0; mi < 4; ++mi)
#pragma unroll
            for (int ni = 0; ni < 4; ++ni)
#pragma unroll
                for (int s = 0; s < 4; ++s) acc[mi][ni][s] = 0.f;

        // m2 for this thread's 8 m columns
        float m2c[4][2];
        {
            int mb = t * 128 + wx * 32 + (lane & 3) * 2;
#pragma unroll
            for (int ni = 0; ni < 4; ++ni) {
                m2c[ni][0] = __ldg(&g_m2[mb + ni * 8]);
                m2c[ni][1] = __ldg(&g_m2[mb + ni * 8 + 1]);
            }
        }

        for (int kc = 0; kc < NKC; ++kc) {
            asm volatile("cp.async.wait_group 0;" ::: "memory");
            __syncthreads();

            // prefetch next chunk into the other buffer
            int nn = cnt + 1;
            if (nn < TILES * NKC) {
                const unsigned char* src = g_B + (size_t)nn * CHUNK_BYTES;
                uint32_t dst = sb + BS_OFF + (uint32_t)(nn & 1) * CHUNK_BYTES;
#pragma unroll
                for (int p = 0; p < 4; ++p)
                    cpa16(dst + p * 4096 + tid * 16, src + p * 4096 + tid * 16);
            }
            asm volatile("cp.async.commit_group;" ::: "memory");

            const uint32_t kcoff  = (uint32_t)kc * CHUNK_BYTES;
            const uint32_t bufoff = (uint32_t)(cnt & 1) * CHUNK_BYTES;
#pragma unroll
            for (int kt = 0; kt < 4; ++kt) {
                uint32_t a[4][4];
#pragma unroll
                for (int mi = 0; mi < 4; ++mi) {
                    uint32_t addr = abase[mi] + kcoff + (uint32_t)((((kt * 2 + cb) ^ axor[mi])) << 4);
                    LDSM_X4(a[mi][0], a[mi][1], a[mi][2], a[mi][3], addr);
                }
                uint32_t b[2][4];
#pragma unroll
                for (int nh = 0; nh < 2; ++nh) {
                    uint32_t addr = bbase[nh] + bufoff + (uint32_t)((((kt * 2 + cb) ^ bxor[nh])) << 4);
                    LDSM_X4(b[nh][0], b[nh][1], b[nh][2], b[nh][3], addr);
                }
#pragma unroll
                for (int mi = 0; mi < 4; ++mi)
#pragma unroll
                    for (int ni = 0; ni < 4; ++ni) {
                        int nh = ni >> 1, sub = ni & 1;
                        MMA16816(acc[mi][ni], a[mi], b[nh][sub], b[nh][sub + 2]);
                    }
            }
            ++cnt;
        }

        // ---- epilogue: stage m2 - 2 q.m to Dist[m][q], then split scan ----
        {
            int g0  = lane >> 2;
            int cp2 = (lane & 3) * 2;
#pragma unroll
            for (int mi = 0; mi < 4; ++mi) {
                int q0 = wq * 64 + mi * 16 + g0;
#pragma unroll
                for (int ni = 0; ni < 4; ++ni) {
                    int m0 = wx * 32 + ni * 8 + cp2;
                    Dist[m0 * PITCH + q0]             = acc[mi][ni][0] + m2c[ni][0];
                    Dist[(m0 + 1) * PITCH + q0]       = acc[mi][ni][1] + m2c[ni][1];
                    Dist[m0 * PITCH + q0 + 8]         = acc[mi][ni][2] + m2c[ni][0];
                    Dist[(m0 + 1) * PITCH + q0 + 8]   = acc[mi][ni][3] + m2c[ni][1];
                }
            }
        }
        __syncthreads();
        {
            const int mbase = t * 128 + scan_h * 64;
            const float* col = Dist + (size_t)(scan_h * 64) * PITCH + scan_q;
#pragma unroll 4
            for (int j = 0; j < 64; ++j) {
                float c = col[j * PITCH];
                if (c < best[KNN - 1]) {
                    best[KNN - 1] = c;
                    bidx[KNN - 1] = mbase + j;
#pragma unroll
                    for (int s = KNN - 1; s > 0; --s) {
                        if (best[s] < best[s - 1]) {
                            float tf = best[s]; best[s] = best[s - 1]; best[s - 1] = tf;
                            int   ti = bidx[s]; bidx[s] = bidx[s - 1]; bidx[s - 1] = ti;
                        }
                    }
                }
            }
        }
        // next tile's first kc-sync orders this scan vs. the next Dist writes
    }

    // ---- merge the two half-scans and finalize ----
    __syncthreads();
    float* mgF = Dist;                       // reuse Dist region
    int*   mgI = reinterpret_cast<int*>(Dist + 128 * KNN);
    if (tid >= 128) {
#pragma unroll
        for (int s = 0; s < KNN; ++s) {
            mgF[scan_q * KNN + s] = best[s];
            mgI[scan_q * KNN + s] = bidx[s];
        }
    }
    __syncthreads();
    if (tid < 128) {
#pragma unroll
        for (int s = 0; s < KNN; ++s) {
            float c = mgF[scan_q * KNN + s];
            if (c < best[KNN - 1]) {
                int ci = mgI[scan_q * KNN + s];
                best[KNN - 1] = c;
                bidx[KNN - 1] = ci;
#pragma unroll
                for (int r = KNN - 1; r > 0; --r) {
                    if (best[r] < best[r - 1]) {
                        float tf = best[r]; best[r] = best[r - 1]; best[r - 1] = tf;
                        int   ti = bidx[r]; bidx[r] = bidx[r - 1]; bidx[r - 1] = ti;
                    }
                }
            }
        }

        float d[KNN];
#pragma unroll
        for (int s = 0; s < KNN; ++s)
            d[s] = sqrtf(fmaxf(q2 + best[s], 1e-12f));

        float W = 0.f, wd = 0.f;
#pragma unroll
        for (int s = 0; s < KNN; ++s) {
            float e = expf(d[0] - d[s]);
            W += e; wd += e * d[s];
        }
        wd /= W;

        float ns = 0.f;
#pragma unroll
        for (int s = 0; s < KNN; ++s) ns += scale[bidx[s]];
        ns *= (1.f / KNN);
        float nd = wd / fmaxf(ns, 1e-6f);

        float mean = 0.f;
#pragma unroll
        for (int s = 0; s < KNN; ++s) mean += d[s];
        mean *= (1.f / KNN);
        float var = 0.f;
#pragma unroll
        for (int s = 0; s < KNN; ++s) { float u = d[s] - mean; var = fmaf(u, u, var); }
        var *= (1.f / KNN);
        float cons = sqrtf(fmaxf(var, 0.f)) / fmaxf(mean, 1e-6f);

        out[qbase + tid] = nd * (1.f + 0.5f * cons);
    }
}

// ---------------------------------------------------------------------------
// Launch
// ---------------------------------------------------------------------------
extern "C" void kernel_launch(void* const* d_in, const int* in_sizes, int n_in,
                              void* d_out, int out_size) {
    const float* query = (const float*)d_in[0];
    const float* mbank = (const float*)d_in[1];
    const float* scale = (const float*)d_in[2];
    float* out = (float*)d_out;
    (void)in_sizes; (void)n_in; (void)out_size;

    cudaFuncSetAttribute(knn_main, cudaFuncAttributeMaxDynamicSharedMemorySize, SMEM_TOTAL);

    prepass_kernel<<<NM / 256, 256>>>(mbank);
    knn_main<<<TILES, 256, SMEM_TOTAL>>>(query, scale, out);
}